// round 1
// baseline (speedup 1.0000x reference)
#include <cuda_runtime.h>
#include <math.h>

#define Bb 8
#define Ll 512
#define Dd 1024
#define Hh 16
#define DKk 64
#define DVv 64
#define EPSF 1e-20f

#define BH (Bb*Hh)           // 128
#define NPOS (Bb*Hh*Ll)      // 65536
#define MROWS (Bb*Ll)        // 4096

// ---------------- scratch (static device globals; no allocation) ----------------
__device__ float g_q[NPOS*DKk];          // [B,H,L,DK]
__device__ float g_k[NPOS*DKk];
__device__ float g_v[NPOS*DVv];
__device__ float g_S[(size_t)BH*Ll*Ll];  // scores -> att_s  (134 MB)
__device__ float g_ao[MROWS*Dd];         // attn out reordered [B,L,H*DV]
__device__ float g_pp[8*NPOS];           // prior partials (8 col-tiles)
__device__ float g_dotg[NPOS];
__device__ float g_alpha[NPOS];
__device__ double g_kl;

// ---------------- block reduction helper ----------------
__device__ __forceinline__ float blkred(float v, bool ismax, float* sred) {
    #pragma unroll
    for (int o = 16; o; o >>= 1) {
        float w = __shfl_xor_sync(0xffffffffu, v, o);
        v = ismax ? fmaxf(v, w) : v + w;
    }
    int wid = threadIdx.x >> 5, lid = threadIdx.x & 31;
    int nw = blockDim.x >> 5;
    if (lid == 0) sred[wid] = v;
    __syncthreads();
    if (wid == 0) {
        v = (lid < nw) ? sred[lid] : (ismax ? -3.402823e38f : 0.f);
        #pragma unroll
        for (int o = 16; o; o >>= 1) {
            float w = __shfl_xor_sync(0xffffffffu, v, o);
            v = ismax ? fmaxf(v, w) : v + w;
        }
        if (lid == 0) sred[0] = v;
    }
    __syncthreads();
    float r = sred[0];
    __syncthreads();
    return r;
}

// ---------------- generic 128x128x8 SGEMM (NN), bias, optional head-scatter ----------------
// C[r,c] = sum_k A[r,k]*Bm[k,c] + bias[c]
// scatter=1: write to out[((b*H+h)*L + l)*64 + d] with r=b*L+l, c=h*64+d
__global__ __launch_bounds__(256) void sgemm128(const float* __restrict__ A,
                                                const float* __restrict__ Bm,
                                                const float* __restrict__ bias,
                                                float* __restrict__ C,
                                                int M, int N, int K, int scatter)
{
    __shared__ float As[8][128];
    __shared__ float Bs[8][128];
    int tid = threadIdx.x;
    int row0 = blockIdx.y * 128;
    int col0 = blockIdx.x * 128;
    int tx = tid & 15, ty = tid >> 4;

    float acc[8][8];
    #pragma unroll
    for (int i = 0; i < 8; i++)
        #pragma unroll
        for (int j = 0; j < 8; j++) acc[i][j] = 0.f;

    int arow = tid >> 1, acol = (tid & 1) * 4;
    int brow = tid >> 5, bcol = (tid & 31) * 4;
    const float* Aptr = A + (size_t)(row0 + arow) * K + acol;
    const float* Bptr = Bm + (size_t)brow * N + col0 + bcol;

    for (int kb = 0; kb < K; kb += 8) {
        float4 av = *(const float4*)(Aptr + kb);
        As[acol + 0][arow] = av.x;
        As[acol + 1][arow] = av.y;
        As[acol + 2][arow] = av.z;
        As[acol + 3][arow] = av.w;
        *(float4*)&Bs[brow][bcol] = *(const float4*)(Bptr + (size_t)kb * N);
        __syncthreads();
        #pragma unroll
        for (int kk = 0; kk < 8; kk++) {
            float a[8], b[8];
            *(float4*)(a)     = *(const float4*)&As[kk][ty * 4];
            *(float4*)(a + 4) = *(const float4*)&As[kk][64 + ty * 4];
            *(float4*)(b)     = *(const float4*)&Bs[kk][tx * 4];
            *(float4*)(b + 4) = *(const float4*)&Bs[kk][64 + tx * 4];
            #pragma unroll
            for (int i = 0; i < 8; i++)
                #pragma unroll
                for (int j = 0; j < 8; j++)
                    acc[i][j] = fmaf(a[i], b[j], acc[i][j]);
        }
        __syncthreads();
    }

    #pragma unroll
    for (int i = 0; i < 8; i++) {
        int r = row0 + ((i < 4) ? ty * 4 + i : 64 + ty * 4 + i - 4);
        #pragma unroll
        for (int j = 0; j < 8; j++) {
            int c = col0 + ((j < 4) ? tx * 4 + j : 64 + tx * 4 + j - 4);
            float val = acc[i][j] + bias[c];
            if (scatter) {
                int b_ = r >> 9, l_ = r & 511;
                int h_ = c >> 6, d_ = c & 63;
                C[(((size_t)(b_ * Hh + h_) * Ll) + l_) * 64 + d_] = val;
            } else {
                C[(size_t)r * N + c] = val;
            }
        }
    }
}

// ---------------- prior MLP GEMM: [65536,64] x Wp1[64,1024], fused leaky + Wp2 reduce ----------------
__global__ __launch_bounds__(256) void prior_gemm(const float* __restrict__ Wp1,
                                                  const float* __restrict__ bp1,
                                                  const float* __restrict__ Wp2)
{
    __shared__ float As[8][128];
    __shared__ float Bs[8][128];
    int tid = threadIdx.x;
    int row0 = blockIdx.y * 128;
    int col0 = blockIdx.x * 128;
    int tx = tid & 15, ty = tid >> 4;

    float acc[8][8];
    #pragma unroll
    for (int i = 0; i < 8; i++)
        #pragma unroll
        for (int j = 0; j < 8; j++) acc[i][j] = 0.f;

    int arow = tid >> 1, acol = (tid & 1) * 4;
    int brow = tid >> 5, bcol = (tid & 31) * 4;

    for (int kb = 0; kb < 64; kb += 8) {
        float4 av = *(const float4*)(g_k + (size_t)(row0 + arow) * 64 + kb + acol);
        As[acol + 0][arow] = av.x;
        As[acol + 1][arow] = av.y;
        As[acol + 2][arow] = av.z;
        As[acol + 3][arow] = av.w;
        *(float4*)&Bs[brow][bcol] = *(const float4*)(Wp1 + (size_t)(kb + brow) * 1024 + col0 + bcol);
        __syncthreads();
        #pragma unroll
        for (int kk = 0; kk < 8; kk++) {
            float a[8], b[8];
            *(float4*)(a)     = *(const float4*)&As[kk][ty * 4];
            *(float4*)(a + 4) = *(const float4*)&As[kk][64 + ty * 4];
            *(float4*)(b)     = *(const float4*)&Bs[kk][tx * 4];
            *(float4*)(b + 4) = *(const float4*)&Bs[kk][64 + tx * 4];
            #pragma unroll
            for (int i = 0; i < 8; i++)
                #pragma unroll
                for (int j = 0; j < 8; j++)
                    acc[i][j] = fmaf(a[i], b[j], acc[i][j]);
        }
        __syncthreads();
    }

    // epilogue: leaky(h)+*Wp2, reduce over this tile's 128 cols per row
    #pragma unroll
    for (int i = 0; i < 8; i++) {
        int rl = (i < 4) ? ty * 4 + i : 64 + ty * 4 + i - 4;
        float s = 0.f;
        #pragma unroll
        for (int j = 0; j < 8; j++) {
            int c = col0 + ((j < 4) ? tx * 4 + j : 64 + tx * 4 + j - 4);
            float hv = acc[i][j] + bp1[c];
            hv = (hv >= 0.f) ? hv : 0.01f * hv;
            s = fmaf(hv, Wp2[c], s);
        }
        #pragma unroll
        for (int o = 8; o; o >>= 1) s += __shfl_xor_sync(0xffffffffu, s, o);
        if (tx == 0) g_pp[(size_t)blockIdx.x * NPOS + row0 + rl] = s;
    }
}

__global__ void combine_dotg(const float* __restrict__ bp2) {
    int i = blockIdx.x * 256 + threadIdx.x;
    float s = 0.f;
    #pragma unroll
    for (int t = 0; t < 8; t++) s += g_pp[(size_t)t * NPOS + i];
    g_dotg[i] = s + bp2[0];
}

// ---------------- alpha softmax + per-(b,h) KL constant terms ----------------
__global__ __launch_bounds__(512) void alpha_kernel() {
    __shared__ float sred[32];
    int bh = blockIdx.x;
    int t = threadIdx.x;
    float x = g_dotg[bh * Ll + t];
    float m = blkred(x, true, sred);
    float e = expf(x - m);
    float den = blkred(e, false, sred);
    float a = e / den;
    g_alpha[bh * Ll + t] = a;
    const float lg1 = 0.69314718f;        // gammaln(3)
    const float EG  = 0.5772156649f;
    float C = a * lg1 + 2.f * EG * a + lgammaf(a + EPSF);
    float sc = blkred(C, false, sred);
    if (t == 0) atomicAdd(&g_kl, (double)(512.0f * sc));
}

// ---------------- batched QK^T (NT), scale * sqrt(DK)=8 ----------------
__global__ __launch_bounds__(256) void score_nt() {
    int bh = blockIdx.z;
    const float* A = g_q + (size_t)bh * Ll * DKk;
    const float* Bp = g_k + (size_t)bh * Ll * DKk;
    float* Sp = g_S + (size_t)bh * Ll * Ll;
    __shared__ float As[8][128];
    __shared__ float Bs[8][128];
    int tid = threadIdx.x;
    int row0 = blockIdx.y * 128, col0 = blockIdx.x * 128;
    int tx = tid & 15, ty = tid >> 4;
    float acc[8][8];
    #pragma unroll
    for (int i = 0; i < 8; i++)
        #pragma unroll
        for (int j = 0; j < 8; j++) acc[i][j] = 0.f;
    int arow = tid >> 1, acol = (tid & 1) * 4;
    for (int kb = 0; kb < DKk; kb += 8) {
        float4 av = *(const float4*)(A + (size_t)(row0 + arow) * DKk + kb + acol);
        As[acol + 0][arow] = av.x;
        As[acol + 1][arow] = av.y;
        As[acol + 2][arow] = av.z;
        As[acol + 3][arow] = av.w;
        float4 bv = *(const float4*)(Bp + (size_t)(col0 + arow) * DKk + kb + acol);
        Bs[acol + 0][arow] = bv.x;
        Bs[acol + 1][arow] = bv.y;
        Bs[acol + 2][arow] = bv.z;
        Bs[acol + 3][arow] = bv.w;
        __syncthreads();
        #pragma unroll
        for (int kk = 0; kk < 8; kk++) {
            float a[8], b[8];
            *(float4*)(a)     = *(const float4*)&As[kk][ty * 4];
            *(float4*)(a + 4) = *(const float4*)&As[kk][64 + ty * 4];
            *(float4*)(b)     = *(const float4*)&Bs[kk][tx * 4];
            *(float4*)(b + 4) = *(const float4*)&Bs[kk][64 + tx * 4];
            #pragma unroll
            for (int i = 0; i < 8; i++)
                #pragma unroll
                for (int j = 0; j < 8; j++)
                    acc[i][j] = fmaf(a[i], b[j], acc[i][j]);
        }
        __syncthreads();
    }
    #pragma unroll
    for (int i = 0; i < 8; i++) {
        int r = row0 + ((i < 4) ? ty * 4 + i : 64 + ty * 4 + i - 4);
        #pragma unroll
        for (int j = 0; j < 8; j++) {
            int c = col0 + ((j < 4) ? tx * 4 + j : 64 + tx * 4 + j - 4);
            Sp[(size_t)r * Ll + c] = acc[i][j] * 8.0f;
        }
    }
}

// ---------------- fused row pass: softmax -> logprobs -> Weibull softmax -> KL ----------------
__global__ __launch_bounds__(256) void row_fused(const float* __restrict__ U) {
    __shared__ float sred[32];
    int row = blockIdx.x;          // 0..65535  (= bh*512 + q)
    int bh = row >> 9;
    size_t base = (size_t)row * 512;
    int t = threadIdx.x;

    float s0 = g_S[base + t], s1 = g_S[base + 256 + t];
    float m = blkred(fmaxf(s0, s1), true, sred);
    float e0 = expf(s0 - m), e1 = expf(s1 - m);
    float den = blkred(e0 + e1, false, sred);
    float inv = 1.f / den;
    float p0 = e0 * inv + EPSF, p1 = e1 * inv + EPSF;   // softmax + EPS
    float lp0 = logf(p0), lp1 = logf(p1);               // logprobs (clamped at log EPS)

    float u0 = U[base + t], u1 = U[base + 256 + t];
    float gw0 = logf(-logf(1.f - u0 + EPSF) + EPSF);
    float gw1 = logf(-logf(1.f - u1 + EPSF) + EPSF);
    float t0 = lp0 - lgammaf(3.f + 2.f * gw0);          // 1 + 1/k + gw/k, k=0.5
    float t1 = lp1 - lgammaf(3.f + 2.f * gw1);

    float m2 = blkred(fmaxf(t0, t1), true, sred);
    float q0 = expf(t0 - m2), q1 = expf(t1 - m2);
    float d2 = blkred(q0 + q1, false, sred);
    float i2 = 1.f / d2;
    g_S[base + t] = q0 * i2;
    g_S[base + 256 + t] = q1 * i2;

    float a0 = g_alpha[bh * 512 + t], a1 = g_alpha[bh * 512 + 256 + t];
    float kl = fmaf(-a0, lp0, p0) + fmaf(-a1, lp1, p1);
    float ks = blkred(kl, false, sred);
    if (t == 0) atomicAdd(&g_kl, (double)ks);
}

// ---------------- batched att_s @ V, reorder to [B,L,H*DV] ----------------
__global__ __launch_bounds__(256) void pv_gemm() {
    int bh = blockIdx.y;
    int b_ = bh >> 4, h_ = bh & 15;
    const float* A = g_S + (size_t)bh * Ll * Ll;
    const float* Bv = g_v + (size_t)bh * Ll * DVv;
    __shared__ float As[16][64];
    __shared__ float Bs[16][64];
    int tid = threadIdx.x;
    int tx = tid & 15, ty = tid >> 4;
    int row0 = blockIdx.x * 64;
    float acc[4][4];
    #pragma unroll
    for (int i = 0; i < 4; i++)
        #pragma unroll
        for (int j = 0; j < 4; j++) acc[i][j] = 0.f;
    int arow = tid >> 2, acol = (tid & 3) * 4;
    int brow = tid >> 4, bcol = (tid & 15) * 4;
    for (int kb = 0; kb < Ll; kb += 16) {
        float4 av = *(const float4*)(A + (size_t)(row0 + arow) * Ll + kb + acol);
        As[acol + 0][arow] = av.x;
        As[acol + 1][arow] = av.y;
        As[acol + 2][arow] = av.z;
        As[acol + 3][arow] = av.w;
        *(float4*)&Bs[brow][bcol] = *(const float4*)(Bv + (size_t)(kb + brow) * DVv + bcol);
        __syncthreads();
        #pragma unroll
        for (int kk = 0; kk < 16; kk++) {
            float a[4], b[4];
            *(float4*)a = *(const float4*)&As[kk][ty * 4];
            *(float4*)b = *(const float4*)&Bs[kk][tx * 4];
            #pragma unroll
            for (int i = 0; i < 4; i++)
                #pragma unroll
                for (int j = 0; j < 4; j++)
                    acc[i][j] = fmaf(a[i], b[j], acc[i][j]);
        }
        __syncthreads();
    }
    #pragma unroll
    for (int i = 0; i < 4; i++) {
        int r = row0 + ty * 4 + i;
        #pragma unroll
        for (int j = 0; j < 4; j++) {
            int c = tx * 4 + j;
            g_ao[((size_t)b_ * Ll + r) * Dd + h_ * DVv + c] = acc[i][j];
        }
    }
}

// ---------------- misc ----------------
__global__ void zero_kernel() { g_kl = 0.0; }

__global__ void finalize_kernel(float* out, int out_size) {
    if (out_size > Bb * Ll * Dd)
        out[Bb * Ll * Dd] = (float)(g_kl / 33554432.0);   // mean over B*H*L*L
}

// ---------------- launch ----------------
extern "C" void kernel_launch(void* const* d_in, const int* in_sizes, int n_in,
                              void* d_out, int out_size) {
    const float* queries = (const float*)d_in[0];
    const float* keys    = (const float*)d_in[1];
    const float* values  = (const float*)d_in[2];
    const float* unif    = (const float*)d_in[3];
    const float* Wq = (const float*)d_in[4];
    const float* bq = (const float*)d_in[5];
    const float* Wk = (const float*)d_in[6];
    const float* bk = (const float*)d_in[7];
    const float* Wv = (const float*)d_in[8];
    const float* bv = (const float*)d_in[9];
    const float* Wo = (const float*)d_in[10];
    const float* bo = (const float*)d_in[11];
    const float* Wp1 = (const float*)d_in[12];
    const float* bp1 = (const float*)d_in[13];
    const float* Wp2 = (const float*)d_in[14];
    const float* bp2 = (const float*)d_in[15];
    float* out = (float*)d_out;

    float *pq, *pk, *pv_, *pao;
    cudaGetSymbolAddress((void**)&pq, g_q);
    cudaGetSymbolAddress((void**)&pk, g_k);
    cudaGetSymbolAddress((void**)&pv_, g_v);
    cudaGetSymbolAddress((void**)&pao, g_ao);

    zero_kernel<<<1, 1>>>();

    dim3 gproj(8, 32);   // N/128, M/128 for [4096,1024,1024]
    sgemm128<<<gproj, 256>>>(queries, Wq, bq, pq, MROWS, Dd, Dd, 1);
    sgemm128<<<gproj, 256>>>(keys,    Wk, bk, pk, MROWS, Dd, Dd, 1);
    sgemm128<<<gproj, 256>>>(values,  Wv, bv, pv_, MROWS, Dd, Dd, 1);

    prior_gemm<<<dim3(8, 512), 256>>>(Wp1, bp1, Wp2);
    combine_dotg<<<256, 256>>>(bp2);
    alpha_kernel<<<BH, 512>>>();

    score_nt<<<dim3(4, 4, BH), 256>>>();
    row_fused<<<NPOS, 256>>>(unif);
    pv_gemm<<<dim3(8, BH), 256>>>();

    sgemm128<<<gproj, 256>>>(pao, Wo, bo, out, MROWS, Dd, Dd, 0);
    finalize_kernel<<<1, 1>>>(out, out_size);
}

// round 2
// speedup vs baseline: 1.1546x; 1.1546x over previous
#include <cuda_runtime.h>
#include <math.h>

#define Bb 8
#define Ll 512
#define Dd 1024
#define Hh 16
#define DKk 64
#define DVv 64
#define EPSF 1e-20f

#define BH (Bb*Hh)           // 128
#define NPOS (Bb*Hh*Ll)      // 65536
#define MROWS (Bb*Ll)        // 4096

// ---------------- scratch (static device globals; no allocation) ----------------
__device__ float g_q[NPOS*DKk];          // [B,H,L,DK]  (pre-scaled by 8)
__device__ float g_k[NPOS*DKk];
__device__ float g_v[NPOS*DVv];
__device__ float g_S[(size_t)BH*Ll*Ll];  // scores -> att_s  (134 MB)
__device__ float g_ao[MROWS*Dd];         // attn out reordered [B,L,H*DV]
__device__ float g_pp[8*NPOS];           // prior partials (8 col-tiles)
__device__ float g_dotg[NPOS];
__device__ float g_alpha[NPOS];
__device__ double g_kl;

// ---------------- block reduction helper ----------------
__device__ __forceinline__ float blkred(float v, bool ismax, float* sred) {
    #pragma unroll
    for (int o = 16; o; o >>= 1) {
        float w = __shfl_xor_sync(0xffffffffu, v, o);
        v = ismax ? fmaxf(v, w) : v + w;
    }
    int wid = threadIdx.x >> 5, lid = threadIdx.x & 31;
    int nw = blockDim.x >> 5;
    if (lid == 0) sred[wid] = v;
    __syncthreads();
    if (wid == 0) {
        v = (lid < nw) ? sred[lid] : (ismax ? -3.402823e38f : 0.f);
        #pragma unroll
        for (int o = 16; o; o >>= 1) {
            float w = __shfl_xor_sync(0xffffffffu, v, o);
            v = ismax ? fmaxf(v, w) : v + w;
        }
        if (lid == 0) sred[0] = v;
    }
    __syncthreads();
    float r = sred[0];
    __syncthreads();
    return r;
}

// ---------------- fast branchless lgamma for x in [-90, 11] ----------------
// reflection for x<0.5, predicated push-up to z>=8, 3-term Stirling.
__device__ __forceinline__ float lgamma_fast(float x) {
    bool refl = (x < 0.5f);
    float z = refl ? 1.0f - x : x;       // z in [0.5, ~91]
    float p = 1.0f;
    #pragma unroll
    for (int i = 0; i < 8; i++) {
        if (z < 8.0f) { p *= z; z += 1.0f; }
    }
    float invz  = 1.0f / z;
    float invz2 = invz * invz;
    float lz = __logf(z);
    float lg = (z - 0.5f) * lz - z + 0.91893853320467274f
             + invz * (8.3333333333e-2f
             + invz2 * (-2.7777777778e-3f + 7.9365079365e-4f * invz2));
    lg -= __logf(p);
    if (refl) {
        float s = sinpif(x);
        lg = 1.1447298858494002f - __logf(fabsf(s)) - lg;   // log(pi) - log|sin(pi x)| - lgamma(1-x)
    }
    return lg;
}

// ---------------- 128x128x8 SGEMM (NN), double-buffered, bias, scale, head-scatter ----------------
__global__ __launch_bounds__(256, 2) void sgemm128(const float* __restrict__ A,
                                                   const float* __restrict__ Bm,
                                                   const float* __restrict__ bias,
                                                   float* __restrict__ C,
                                                   int M, int N, int K, int scatter,
                                                   float scale)
{
    __shared__ float As[2][8][128];
    __shared__ float Bs[2][8][128];
    int tid = threadIdx.x;
    int row0 = blockIdx.y * 128;
    int col0 = blockIdx.x * 128;
    int tx = tid & 15, ty = tid >> 4;

    float acc[8][8];
    #pragma unroll
    for (int i = 0; i < 8; i++)
        #pragma unroll
        for (int j = 0; j < 8; j++) acc[i][j] = 0.f;

    int arow = tid >> 1, acol = (tid & 1) * 4;
    int brow = tid >> 5, bcol = (tid & 31) * 4;
    const float* Aptr = A + (size_t)(row0 + arow) * K + acol;
    const float* Bptr = Bm + (size_t)brow * N + col0 + bcol;
    int nk = K >> 3;

    // preload k-block 0
    {
        float4 av = *(const float4*)(Aptr);
        As[0][acol + 0][arow] = av.x;
        As[0][acol + 1][arow] = av.y;
        As[0][acol + 2][arow] = av.z;
        As[0][acol + 3][arow] = av.w;
        *(float4*)&Bs[0][brow][bcol] = *(const float4*)(Bptr);
    }
    __syncthreads();

    for (int kb = 0; kb < nk; kb++) {
        int cur = kb & 1;
        float4 av2, bv2;
        bool more = (kb + 1 < nk);
        if (more) {
            av2 = *(const float4*)(Aptr + (kb + 1) * 8);
            bv2 = *(const float4*)(Bptr + (size_t)(kb + 1) * 8 * N);
        }
        #pragma unroll
        for (int kk = 0; kk < 8; kk++) {
            float a[8], b[8];
            *(float4*)(a)     = *(const float4*)&As[cur][kk][ty * 4];
            *(float4*)(a + 4) = *(const float4*)&As[cur][kk][64 + ty * 4];
            *(float4*)(b)     = *(const float4*)&Bs[cur][kk][tx * 4];
            *(float4*)(b + 4) = *(const float4*)&Bs[cur][kk][64 + tx * 4];
            #pragma unroll
            for (int i = 0; i < 8; i++)
                #pragma unroll
                for (int j = 0; j < 8; j++)
                    acc[i][j] = fmaf(a[i], b[j], acc[i][j]);
        }
        if (more) {
            int nxt = cur ^ 1;
            As[nxt][acol + 0][arow] = av2.x;
            As[nxt][acol + 1][arow] = av2.y;
            As[nxt][acol + 2][arow] = av2.z;
            As[nxt][acol + 3][arow] = av2.w;
            *(float4*)&Bs[nxt][brow][bcol] = bv2;
            __syncthreads();
        }
    }

    #pragma unroll
    for (int i = 0; i < 8; i++) {
        int r = row0 + ((i < 4) ? ty * 4 + i : 64 + ty * 4 + i - 4);
        #pragma unroll
        for (int j = 0; j < 8; j++) {
            int c = col0 + ((j < 4) ? tx * 4 + j : 64 + tx * 4 + j - 4);
            float val = (acc[i][j] + bias[c]) * scale;
            if (scatter) {
                int b_ = r >> 9, l_ = r & 511;
                int h_ = c >> 6, d_ = c & 63;
                C[(((size_t)(b_ * Hh + h_) * Ll) + l_) * 64 + d_] = val;
            } else {
                C[(size_t)r * N + c] = val;
            }
        }
    }
}

// ---------------- prior MLP GEMM: [65536,64] x Wp1[64,1024], fused leaky + Wp2 reduce ----------------
__global__ __launch_bounds__(256, 2) void prior_gemm(const float* __restrict__ Wp1,
                                                     const float* __restrict__ bp1,
                                                     const float* __restrict__ Wp2)
{
    __shared__ float As[2][8][128];
    __shared__ float Bs[2][8][128];
    int tid = threadIdx.x;
    int row0 = blockIdx.y * 128;
    int col0 = blockIdx.x * 128;
    int tx = tid & 15, ty = tid >> 4;

    float acc[8][8];
    #pragma unroll
    for (int i = 0; i < 8; i++)
        #pragma unroll
        for (int j = 0; j < 8; j++) acc[i][j] = 0.f;

    int arow = tid >> 1, acol = (tid & 1) * 4;
    int brow = tid >> 5, bcol = (tid & 31) * 4;
    const float* Aptr = g_k + (size_t)(row0 + arow) * 64 + acol;
    const float* Bptr = Wp1 + (size_t)brow * 1024 + col0 + bcol;

    {
        float4 av = *(const float4*)(Aptr);
        As[0][acol + 0][arow] = av.x;
        As[0][acol + 1][arow] = av.y;
        As[0][acol + 2][arow] = av.z;
        As[0][acol + 3][arow] = av.w;
        *(float4*)&Bs[0][brow][bcol] = *(const float4*)(Bptr);
    }
    __syncthreads();

    for (int kb = 0; kb < 8; kb++) {
        int cur = kb & 1;
        float4 av2, bv2;
        bool more = (kb + 1 < 8);
        if (more) {
            av2 = *(const float4*)(Aptr + (kb + 1) * 8);
            bv2 = *(const float4*)(Bptr + (size_t)(kb + 1) * 8 * 1024);
        }
        #pragma unroll
        for (int kk = 0; kk < 8; kk++) {
            float a[8], b[8];
            *(float4*)(a)     = *(const float4*)&As[cur][kk][ty * 4];
            *(float4*)(a + 4) = *(const float4*)&As[cur][kk][64 + ty * 4];
            *(float4*)(b)     = *(const float4*)&Bs[cur][kk][tx * 4];
            *(float4*)(b + 4) = *(const float4*)&Bs[cur][kk][64 + tx * 4];
            #pragma unroll
            for (int i = 0; i < 8; i++)
                #pragma unroll
                for (int j = 0; j < 8; j++)
                    acc[i][j] = fmaf(a[i], b[j], acc[i][j]);
        }
        if (more) {
            int nxt = cur ^ 1;
            As[nxt][acol + 0][arow] = av2.x;
            As[nxt][acol + 1][arow] = av2.y;
            As[nxt][acol + 2][arow] = av2.z;
            As[nxt][acol + 3][arow] = av2.w;
            *(float4*)&Bs[nxt][brow][bcol] = bv2;
            __syncthreads();
        }
    }

    // epilogue: leaky(h)+*Wp2, reduce over this tile's 128 cols per row
    #pragma unroll
    for (int i = 0; i < 8; i++) {
        int rl = (i < 4) ? ty * 4 + i : 64 + ty * 4 + i - 4;
        float s = 0.f;
        #pragma unroll
        for (int j = 0; j < 8; j++) {
            int c = col0 + ((j < 4) ? tx * 4 + j : 64 + tx * 4 + j - 4);
            float hv = acc[i][j] + bp1[c];
            hv = (hv >= 0.f) ? hv : 0.01f * hv;
            s = fmaf(hv, Wp2[c], s);
        }
        #pragma unroll
        for (int o = 8; o; o >>= 1) s += __shfl_xor_sync(0xffffffffu, s, o);
        if (tx == 0) g_pp[(size_t)blockIdx.x * NPOS + row0 + rl] = s;
    }
}

__global__ void combine_dotg(const float* __restrict__ bp2) {
    int i = blockIdx.x * 256 + threadIdx.x;
    float s = 0.f;
    #pragma unroll
    for (int t = 0; t < 8; t++) s += g_pp[(size_t)t * NPOS + i];
    g_dotg[i] = s + bp2[0];
}

// ---------------- alpha softmax + per-(b,h) KL constant terms ----------------
__global__ __launch_bounds__(512) void alpha_kernel() {
    __shared__ float sred[32];
    int bh = blockIdx.x;
    int t = threadIdx.x;
    float x = g_dotg[bh * Ll + t];
    float m = blkred(x, true, sred);
    float e = expf(x - m);
    float den = blkred(e, false, sred);
    float a = e / den;
    g_alpha[bh * Ll + t] = a;
    const float lg1 = 0.69314718f;        // gammaln(3)
    const float EG  = 0.5772156649f;
    float C = a * lg1 + 2.f * EG * a + lgammaf(a + EPSF);
    float sc = blkred(C, false, sred);
    if (t == 0) atomicAdd(&g_kl, (double)(512.0f * sc));
}

// ---------------- batched QK^T (NT), double-buffered; q pre-scaled by 8 ----------------
__global__ __launch_bounds__(256, 2) void score_nt() {
    int bh = blockIdx.z;
    const float* A  = g_q + (size_t)bh * Ll * DKk;
    const float* Bp = g_k + (size_t)bh * Ll * DKk;
    float* Sp = g_S + (size_t)bh * Ll * Ll;
    __shared__ float As[2][8][128];
    __shared__ float Bs[2][8][128];
    int tid = threadIdx.x;
    int row0 = blockIdx.y * 128, col0 = blockIdx.x * 128;
    int tx = tid & 15, ty = tid >> 4;
    float acc[8][8];
    #pragma unroll
    for (int i = 0; i < 8; i++)
        #pragma unroll
        for (int j = 0; j < 8; j++) acc[i][j] = 0.f;
    int arow = tid >> 1, acol = (tid & 1) * 4;
    const float* Aptr = A  + (size_t)(row0 + arow) * DKk + acol;
    const float* Bptr = Bp + (size_t)(col0 + arow) * DKk + acol;

    {
        float4 av = *(const float4*)(Aptr);
        As[0][acol + 0][arow] = av.x;
        As[0][acol + 1][arow] = av.y;
        As[0][acol + 2][arow] = av.z;
        As[0][acol + 3][arow] = av.w;
        float4 bv = *(const float4*)(Bptr);
        Bs[0][acol + 0][arow] = bv.x;
        Bs[0][acol + 1][arow] = bv.y;
        Bs[0][acol + 2][arow] = bv.z;
        Bs[0][acol + 3][arow] = bv.w;
    }
    __syncthreads();

    for (int kb = 0; kb < 8; kb++) {
        int cur = kb & 1;
        float4 av2, bv2;
        bool more = (kb + 1 < 8);
        if (more) {
            av2 = *(const float4*)(Aptr + (kb + 1) * 8);
            bv2 = *(const float4*)(Bptr + (kb + 1) * 8);
        }
        #pragma unroll
        for (int kk = 0; kk < 8; kk++) {
            float a[8], b[8];
            *(float4*)(a)     = *(const float4*)&As[cur][kk][ty * 4];
            *(float4*)(a + 4) = *(const float4*)&As[cur][kk][64 + ty * 4];
            *(float4*)(b)     = *(const float4*)&Bs[cur][kk][tx * 4];
            *(float4*)(b + 4) = *(const float4*)&Bs[cur][kk][64 + tx * 4];
            #pragma unroll
            for (int i = 0; i < 8; i++)
                #pragma unroll
                for (int j = 0; j < 8; j++)
                    acc[i][j] = fmaf(a[i], b[j], acc[i][j]);
        }
        if (more) {
            int nxt = cur ^ 1;
            As[nxt][acol + 0][arow] = av2.x;
            As[nxt][acol + 1][arow] = av2.y;
            As[nxt][acol + 2][arow] = av2.z;
            As[nxt][acol + 3][arow] = av2.w;
            Bs[nxt][acol + 0][arow] = bv2.x;
            Bs[nxt][acol + 1][arow] = bv2.y;
            Bs[nxt][acol + 2][arow] = bv2.z;
            Bs[nxt][acol + 3][arow] = bv2.w;
            __syncthreads();
        }
    }
    #pragma unroll
    for (int i = 0; i < 8; i++) {
        int r = row0 + ((i < 4) ? ty * 4 + i : 64 + ty * 4 + i - 4);
        #pragma unroll
        for (int j = 0; j < 8; j++) {
            int c = col0 + ((j < 4) ? tx * 4 + j : 64 + tx * 4 + j - 4);
            Sp[(size_t)r * Ll + c] = acc[i][j];
        }
    }
}

// ---------------- fused row pass: softmax -> logprobs -> Weibull softmax -> KL ----------------
__global__ __launch_bounds__(256) void row_fused(const float* __restrict__ U) {
    __shared__ float sred[32];
    int row = blockIdx.x;          // 0..65535  (= bh*512 + q)
    int bh = row >> 9;
    size_t base = (size_t)row * 512;
    int t = threadIdx.x;

    float s0 = g_S[base + t], s1 = g_S[base + 256 + t];
    float m = blkred(fmaxf(s0, s1), true, sred);
    float e0 = __expf(s0 - m), e1 = __expf(s1 - m);
    float den = blkred(e0 + e1, false, sred);
    float inv = 1.f / den;
    float logden = __logf(den);
    float p0 = e0 * inv, p1 = e1 * inv;
    float r0 = s0 - m - logden, r1 = s1 - m - logden;
    // logprobs with the EPS clamp: log(p + 1e-20)
    float lp0 = (r0 >= -36.f) ? r0 : __logf(p0 + EPSF);
    float lp1 = (r1 >= -36.f) ? r1 : __logf(p1 + EPSF);

    float u0 = U[base + t], u1 = U[base + 256 + t];
    // accurate inner log (relative accuracy needed for tiny -log(1-u))
    float w0 = -logf(1.f - u0 + EPSF);
    float w1 = -logf(1.f - u1 + EPSF);
    float gw0 = __logf(w0 + EPSF);
    float gw1 = __logf(w1 + EPSF);
    float t0 = lp0 - lgamma_fast(3.f + 2.f * gw0);   // 1 + 1/k + gw/k, k=0.5
    float t1 = lp1 - lgamma_fast(3.f + 2.f * gw1);

    float m2 = blkred(fmaxf(t0, t1), true, sred);
    float q0 = __expf(t0 - m2), q1 = __expf(t1 - m2);
    float d2 = blkred(q0 + q1, false, sred);
    float i2 = 1.f / d2;
    g_S[base + t] = q0 * i2;
    g_S[base + 256 + t] = q1 * i2;

    float a0 = g_alpha[bh * 512 + t], a1 = g_alpha[bh * 512 + 256 + t];
    float kl = fmaf(-a0, lp0, p0) + fmaf(-a1, lp1, p1);
    float ks = blkred(kl, false, sred);
    if (t == 0) atomicAdd(&g_kl, (double)ks);
}

// ---------------- batched att_s @ V (128x64 tiles, double-buffered), reorder to [B,L,H*DV] ----------------
__global__ __launch_bounds__(256, 2) void pv_gemm() {
    int bh = blockIdx.y;
    int b_ = bh >> 4, h_ = bh & 15;
    const float* A  = g_S + (size_t)bh * Ll * Ll;
    const float* Bv = g_v + (size_t)bh * Ll * DVv;
    __shared__ float As[2][16][128];
    __shared__ float Bs[2][16][64];
    int tid = threadIdx.x;
    int tx = tid & 15, ty = tid >> 4;
    int row0 = blockIdx.x * 128;
    float acc[8][4];
    #pragma unroll
    for (int i = 0; i < 8; i++)
        #pragma unroll
        for (int j = 0; j < 4; j++) acc[i][j] = 0.f;

    int arow = tid >> 1, acol = (tid & 1) * 8;
    int brow = tid >> 4, bcol = (tid & 15) * 4;
    const float* Aptr = A + (size_t)(row0 + arow) * Ll + acol;
    const float* Bptr = Bv + (size_t)brow * DVv + bcol;

    {
        float4 a0 = *(const float4*)(Aptr);
        float4 a1 = *(const float4*)(Aptr + 4);
        As[0][acol + 0][arow] = a0.x;
        As[0][acol + 1][arow] = a0.y;
        As[0][acol + 2][arow] = a0.z;
        As[0][acol + 3][arow] = a0.w;
        As[0][acol + 4][arow] = a1.x;
        As[0][acol + 5][arow] = a1.y;
        As[0][acol + 6][arow] = a1.z;
        As[0][acol + 7][arow] = a1.w;
        *(float4*)&Bs[0][brow][bcol] = *(const float4*)(Bptr);
    }
    __syncthreads();

    for (int kb = 0; kb < 32; kb++) {     // 512 / 16
        int cur = kb & 1;
        float4 a0n, a1n, bvn;
        bool more = (kb + 1 < 32);
        if (more) {
            a0n = *(const float4*)(Aptr + (kb + 1) * 16);
            a1n = *(const float4*)(Aptr + (kb + 1) * 16 + 4);
            bvn = *(const float4*)(Bptr + (size_t)(kb + 1) * 16 * DVv);
        }
        #pragma unroll
        for (int kk = 0; kk < 16; kk++) {
            float a[8], b[4];
            *(float4*)(a)     = *(const float4*)&As[cur][kk][ty * 4];
            *(float4*)(a + 4) = *(const float4*)&As[cur][kk][64 + ty * 4];
            *(float4*)(b)     = *(const float4*)&Bs[cur][kk][tx * 4];
            #pragma unroll
            for (int i = 0; i < 8; i++)
                #pragma unroll
                for (int j = 0; j < 4; j++)
                    acc[i][j] = fmaf(a[i], b[j], acc[i][j]);
        }
        if (more) {
            int nxt = cur ^ 1;
            As[nxt][acol + 0][arow] = a0n.x;
            As[nxt][acol + 1][arow] = a0n.y;
            As[nxt][acol + 2][arow] = a0n.z;
            As[nxt][acol + 3][arow] = a0n.w;
            As[nxt][acol + 4][arow] = a1n.x;
            As[nxt][acol + 5][arow] = a1n.y;
            As[nxt][acol + 6][arow] = a1n.z;
            As[nxt][acol + 7][arow] = a1n.w;
            *(float4*)&Bs[nxt][brow][bcol] = bvn;
            __syncthreads();
        }
    }

    #pragma unroll
    for (int i = 0; i < 8; i++) {
        int r = row0 + ((i < 4) ? ty * 4 + i : 64 + ty * 4 + i - 4);
        #pragma unroll
        for (int j = 0; j < 4; j++) {
            int c = tx * 4 + j;
            g_ao[((size_t)b_ * Ll + r) * Dd + h_ * DVv + c] = acc[i][j];
        }
    }
}

// ---------------- misc ----------------
__global__ void zero_kernel() { g_kl = 0.0; }

__global__ void finalize_kernel(float* out, int out_size) {
    if (out_size > Bb * Ll * Dd)
        out[Bb * Ll * Dd] = (float)(g_kl / 33554432.0);   // mean over B*H*L*L
}

// ---------------- launch ----------------
extern "C" void kernel_launch(void* const* d_in, const int* in_sizes, int n_in,
                              void* d_out, int out_size) {
    const float* queries = (const float*)d_in[0];
    const float* keys    = (const float*)d_in[1];
    const float* values  = (const float*)d_in[2];
    const float* unif    = (const float*)d_in[3];
    const float* Wq = (const float*)d_in[4];
    const float* bq = (const float*)d_in[5];
    const float* Wk = (const float*)d_in[6];
    const float* bk = (const float*)d_in[7];
    const float* Wv = (const float*)d_in[8];
    const float* bv = (const float*)d_in[9];
    const float* Wo = (const float*)d_in[10];
    const float* bo = (const float*)d_in[11];
    const float* Wp1 = (const float*)d_in[12];
    const float* bp1 = (const float*)d_in[13];
    const float* Wp2 = (const float*)d_in[14];
    const float* bp2 = (const float*)d_in[15];
    float* out = (float*)d_out;

    float *pq, *pk, *pv_, *pao;
    cudaGetSymbolAddress((void**)&pq, g_q);
    cudaGetSymbolAddress((void**)&pk, g_k);
    cudaGetSymbolAddress((void**)&pv_, g_v);
    cudaGetSymbolAddress((void**)&pao, g_ao);

    zero_kernel<<<1, 1>>>();

    dim3 gproj(8, 32);   // N/128, M/128 for [4096,1024,1024]
    // q pre-scaled by 8 = sqrt(DK) (ref divides by 1/sqrt(dk))
    sgemm128<<<gproj, 256>>>(queries, Wq, bq, pq, MROWS, Dd, Dd, 1, 8.0f);
    sgemm128<<<gproj, 256>>>(keys,    Wk, bk, pk, MROWS, Dd, Dd, 1, 1.0f);
    sgemm128<<<gproj, 256>>>(values,  Wv, bv, pv_, MROWS, Dd, Dd, 1, 1.0f);

    prior_gemm<<<dim3(8, 512), 256>>>(Wp1, bp1, Wp2);
    combine_dotg<<<256, 256>>>(bp2);
    alpha_kernel<<<BH, 512>>>();

    score_nt<<<dim3(4, 4, BH), 256>>>();
    row_fused<<<NPOS, 256>>>(unif);
    pv_gemm<<<dim3(4, BH), 256>>>();

    sgemm128<<<gproj, 256>>>(pao, Wo, bo, out, MROWS, Dd, Dd, 0, 1.0f);
    finalize_kernel<<<1, 1>>>(out, out_size);
}